// round 2
// baseline (speedup 1.0000x reference)
#include <cuda_runtime.h>
#include <cuda_bf16.h>
#include <math_constants.h>

// ---------------------------------------------------------------------------
// MHA_962072674722: b=2, s=2048, dim=1024, 16 heads x 64
//   QKV = q @ [Wq|Wkv] + [bq|bkv]      -> g_QKV [4096, 3072] (Q|K|V)
//   attn per (b,h): softmax(QK^T/8) V  -> g_ATT [4096, 1024]
//   out = g_ATT @ Wo + bo              -> d_out [4096, 1024]
// ---------------------------------------------------------------------------

__device__ float g_QKV[4096 * 3072];   // 48 MB scratch (static: allocation-guard safe)
__device__ float g_ATT[4096 * 1024];   // 16 MB scratch

// ---------------------------------------------------------------------------
// Classic SGEMM: C[M,N] = A[M,K] @ B[K,N] + bias, 128x128x8 tile, 8x8 microtile
// M, N multiples of 128; K multiple of 8. 256 threads.
// ---------------------------------------------------------------------------
__global__ __launch_bounds__(256) void sgemm_bias(
    const float* __restrict__ A, int lda,
    const float* __restrict__ B, int ldb,
    const float* __restrict__ bias,
    float* __restrict__ C, int ldc,
    int K)
{
    __shared__ float As[8][128];
    __shared__ float Bs[8][128];

    const int tid   = threadIdx.x;
    const int m0    = blockIdx.y * 128;
    const int n0    = blockIdx.x * 128;
    const int a_row = tid >> 1;          // 0..127
    const int a_col = (tid & 1) * 4;     // 0 or 4
    const int b_row = tid >> 5;          // 0..7
    const int b_col = (tid & 31) * 4;    // 0..124
    const int ty    = tid >> 4;          // 0..15
    const int tx    = tid & 15;          // 0..15

    float acc[8][8];
#pragma unroll
    for (int i = 0; i < 8; i++)
#pragma unroll
        for (int j = 0; j < 8; j++) acc[i][j] = 0.f;

    for (int k0 = 0; k0 < K; k0 += 8) {
        float4 av = *reinterpret_cast<const float4*>(
            A + (size_t)(m0 + a_row) * lda + k0 + a_col);
        As[a_col + 0][a_row] = av.x;
        As[a_col + 1][a_row] = av.y;
        As[a_col + 2][a_row] = av.z;
        As[a_col + 3][a_row] = av.w;
        *reinterpret_cast<float4*>(&Bs[b_row][b_col]) =
            *reinterpret_cast<const float4*>(
                B + (size_t)(k0 + b_row) * ldb + n0 + b_col);
        __syncthreads();

#pragma unroll
        for (int k = 0; k < 8; k++) {
            float a[8], b[8];
            *reinterpret_cast<float4*>(&a[0]) = *reinterpret_cast<float4*>(&As[k][ty * 8]);
            *reinterpret_cast<float4*>(&a[4]) = *reinterpret_cast<float4*>(&As[k][ty * 8 + 4]);
            *reinterpret_cast<float4*>(&b[0]) = *reinterpret_cast<float4*>(&Bs[k][tx * 8]);
            *reinterpret_cast<float4*>(&b[4]) = *reinterpret_cast<float4*>(&Bs[k][tx * 8 + 4]);
#pragma unroll
            for (int i = 0; i < 8; i++)
#pragma unroll
                for (int j = 0; j < 8; j++)
                    acc[i][j] = fmaf(a[i], b[j], acc[i][j]);
        }
        __syncthreads();
    }

    float bias_r[8];
#pragma unroll
    for (int j = 0; j < 8; j++) bias_r[j] = bias[n0 + tx * 8 + j];

#pragma unroll
    for (int i = 0; i < 8; i++) {
        float* cp = C + (size_t)(m0 + ty * 8 + i) * ldc + n0 + tx * 8;
        float4 v0 = make_float4(acc[i][0] + bias_r[0], acc[i][1] + bias_r[1],
                                acc[i][2] + bias_r[2], acc[i][3] + bias_r[3]);
        float4 v1 = make_float4(acc[i][4] + bias_r[4], acc[i][5] + bias_r[5],
                                acc[i][6] + bias_r[6], acc[i][7] + bias_r[7]);
        *reinterpret_cast<float4*>(cp)     = v0;
        *reinterpret_cast<float4*>(cp + 4) = v1;
    }
}

// ---------------------------------------------------------------------------
// Flash attention: grid (16 qtiles, 16 heads, 2 batch), 128 threads.
// Thread = 1 query row. Q row + O accumulator in registers; K/V tiles in smem.
// All inner-loop smem reads are warp-broadcast (same [j][d] for every lane).
// ---------------------------------------------------------------------------
__global__ __launch_bounds__(128) void attn_kernel()
{
    __shared__ float Ks[64][68];   // pad 68: float4-aligned, conflict-light stores
    __shared__ float Vs[64][68];

    const int b   = blockIdx.z;
    const int h   = blockIdx.y;
    const int qt  = blockIdx.x;
    const int tid = threadIdx.x;
    const int row = b * 2048 + qt * 128 + tid;

    const float* qp = g_QKV + (size_t)row * 3072 + h * 64;
    float qreg[64];
#pragma unroll
    for (int d = 0; d < 64; d += 4) {
        float4 v = *reinterpret_cast<const float4*>(qp + d);
        qreg[d] = v.x; qreg[d + 1] = v.y; qreg[d + 2] = v.z; qreg[d + 3] = v.w;
    }

    float m = -CUDART_INF_F, l = 0.f;
    float o[64];
#pragma unroll
    for (int d = 0; d < 64; d++) o[d] = 0.f;

    const float scale = 0.125f;          // 64^-0.5
    const int lr = tid >> 1;             // 0..63 : K/V row this thread stages
    const int lc = (tid & 1) * 32;       // half-row

    for (int kt = 0; kt < 32; kt++) {
        const float* kp = g_QKV + (size_t)(b * 2048 + kt * 64 + lr) * 3072
                        + 1024 + h * 64 + lc;
#pragma unroll
        for (int i = 0; i < 32; i += 4) {
            *reinterpret_cast<float4*>(&Ks[lr][lc + i]) =
                *reinterpret_cast<const float4*>(kp + i);
            *reinterpret_cast<float4*>(&Vs[lr][lc + i]) =
                *reinterpret_cast<const float4*>(kp + 1024 + i);
        }
        __syncthreads();

        for (int j = 0; j < 64; j++) {
            float s = 0.f;
#pragma unroll
            for (int d = 0; d < 64; d++) s = fmaf(qreg[d], Ks[j][d], s);
            s *= scale;
            float mnew = fmaxf(m, s);
            float corr = __expf(m - mnew);
            float p    = __expf(s - mnew);
            l = l * corr + p;
#pragma unroll
            for (int d = 0; d < 64; d++)
                o[d] = fmaf(p, Vs[j][d], o[d] * corr);
            m = mnew;
        }
        __syncthreads();
    }

    const float inv = 1.f / l;
    float* op = g_ATT + (size_t)row * 1024 + h * 64;
#pragma unroll
    for (int d = 0; d < 64; d += 4) {
        float4 v = make_float4(o[d] * inv, o[d + 1] * inv,
                               o[d + 2] * inv, o[d + 3] * inv);
        *reinterpret_cast<float4*>(op + d) = v;
    }
}

// ---------------------------------------------------------------------------
extern "C" void kernel_launch(void* const* d_in, const int* in_sizes, int n_in,
                              void* d_out, int out_size)
{
    const float* q   = (const float*)d_in[0];   // [2,2048,1024]
    const float* Wq  = (const float*)d_in[1];   // [1024,1024]
    const float* bq  = (const float*)d_in[2];   // [1024]
    const float* Wkv = (const float*)d_in[3];   // [1024,2048]
    const float* bkv = (const float*)d_in[4];   // [2048]
    const float* Wo  = (const float*)d_in[5];   // [1024,1024]
    const float* bo  = (const float*)d_in[6];   // [1024]
    float* out = (float*)d_out;                 // [2,2048,1024]

    float* qkv = nullptr;
    float* att = nullptr;
    cudaGetSymbolAddress((void**)&qkv, g_QKV);
    cudaGetSymbolAddress((void**)&att, g_ATT);

    // Q projection: cols [0,1024) of g_QKV
    sgemm_bias<<<dim3(1024 / 128, 4096 / 128), 256>>>(
        q, 1024, Wq, 1024, bq, qkv, 3072, 1024);
    // KV projection: cols [1024,3072) of g_QKV
    sgemm_bias<<<dim3(2048 / 128, 4096 / 128), 256>>>(
        q, 1024, Wkv, 2048, bkv, qkv + 1024, 3072, 1024);
    // Attention
    attn_kernel<<<dim3(16, 16, 2), 128>>>();
    // Output projection
    sgemm_bias<<<dim3(1024 / 128, 4096 / 128), 256>>>(
        att, 1024, Wo, 1024, bo, out, 1024, 1024);
}

// round 4
// speedup vs baseline: 1.6912x; 1.6912x over previous
#include <cuda_runtime.h>
#include <cuda_bf16.h>
#include <math_constants.h>

// ---------------------------------------------------------------------------
// MHA_962072674722 (b=2, s=2048, dim=1024, 16 heads x 64) — TF32 tensor cores
//   All GEMMs via mma.sync.m16n8k8 tf32 with split-TF32 for fp32-like accuracy.
// ---------------------------------------------------------------------------

__device__ float g_QKV[4096 * 3072];   // Q|K|V scratch
__device__ float g_ATT[4096 * 1024];   // attention output scratch

// ---- TF32 helpers ---------------------------------------------------------
__device__ __forceinline__ unsigned f2tf(float x) {
    unsigned u;
    asm("cvt.rna.tf32.f32 %0, %1;" : "=r"(u) : "f"(x));
    return u;
}
__device__ __forceinline__ void split_tf(float x, unsigned& h, unsigned& l) {
    h = f2tf(x);
    l = f2tf(x - __uint_as_float(h));
}
__device__ __forceinline__ void mma_tf32(float c[4], const unsigned a[4],
                                         unsigned b0, unsigned b1) {
    asm("mma.sync.aligned.m16n8k8.row.col.f32.tf32.tf32.f32 "
        "{%0,%1,%2,%3},{%4,%5,%6,%7},{%8,%9},{%0,%1,%2,%3};"
        : "+f"(c[0]), "+f"(c[1]), "+f"(c[2]), "+f"(c[3])
        : "r"(a[0]), "r"(a[1]), "r"(a[2]), "r"(a[3]), "r"(b0), "r"(b1));
}

// ---------------------------------------------------------------------------
// 3xTF32 GEMM: C[M,N] = A[M,K] @ B[K,N] + bias.  128x128 block tile, k-tile 32.
// 8 warps: warp tile 32(m) x 64(n). M,N % 128 == 0, K % 32 == 0.
// ---------------------------------------------------------------------------
__global__ __launch_bounds__(256) void gemm_tf32x3(
    const float* __restrict__ A, int lda,
    const float* __restrict__ B, int ldb,
    const float* __restrict__ bias,
    float* __restrict__ C, int ldc, int K)
{
    __shared__ float As[128][36];   // [m][k], pad 36 -> conflict-free frag loads
    __shared__ float Bs[128][36];   // [n][k] (B transposed on stage)

    const int tid = threadIdx.x, lane = tid & 31, w = tid >> 5;
    const int m0 = blockIdx.y * 128, n0 = blockIdx.x * 128;
    const int wm = (w & 3) * 32, wn = (w >> 2) * 64;
    const int r = lane >> 2, cq = lane & 3;

    float acc[2][8][4];
#pragma unroll
    for (int mt = 0; mt < 2; mt++)
#pragma unroll
        for (int nt = 0; nt < 8; nt++)
#pragma unroll
            for (int i = 0; i < 4; i++) acc[mt][nt][i] = 0.f;

    const int arow = tid >> 1, acb = (tid & 1) * 16;
    const int bkk = tid & 31, bnb = (tid >> 5) * 4;

    for (int k0 = 0; k0 < K; k0 += 32) {
        // stage A [128 x 32] natural
#pragma unroll
        for (int i = 0; i < 4; i++) {
            float4 v = *reinterpret_cast<const float4*>(
                A + (m0 + arow) * lda + k0 + acb + i * 4);
            *reinterpret_cast<float4*>(&As[arow][acb + i * 4]) = v;
        }
        // stage B [128 x 32] transposed -> Bs[n][k]
#pragma unroll
        for (int i = 0; i < 4; i++) {
            int nn = bnb + i * 32;
            float4 v = *reinterpret_cast<const float4*>(
                B + (k0 + bkk) * ldb + n0 + nn);
            Bs[nn + 0][bkk] = v.x; Bs[nn + 1][bkk] = v.y;
            Bs[nn + 2][bkk] = v.z; Bs[nn + 3][bkk] = v.w;
        }
        __syncthreads();

#pragma unroll
        for (int ks = 0; ks < 4; ks++) {
            const int kk = ks * 8;
            unsigned ah[2][4], al[2][4];
#pragma unroll
            for (int mt = 0; mt < 2; mt++) {
                const int mr = wm + mt * 16;
                split_tf(As[mr + r][kk + cq],         ah[mt][0], al[mt][0]);
                split_tf(As[mr + r + 8][kk + cq],     ah[mt][1], al[mt][1]);
                split_tf(As[mr + r][kk + cq + 4],     ah[mt][2], al[mt][2]);
                split_tf(As[mr + r + 8][kk + cq + 4], ah[mt][3], al[mt][3]);
            }
#pragma unroll
            for (int nt = 0; nt < 8; nt++) {
                const int nn = wn + nt * 8 + r;
                unsigned bh0, bl0, bh1, bl1;
                split_tf(Bs[nn][kk + cq],     bh0, bl0);
                split_tf(Bs[nn][kk + cq + 4], bh1, bl1);
#pragma unroll
                for (int mt = 0; mt < 2; mt++) {
                    mma_tf32(acc[mt][nt], ah[mt], bh0, bh1);
                    mma_tf32(acc[mt][nt], ah[mt], bl0, bl1);
                    mma_tf32(acc[mt][nt], al[mt], bh0, bh1);
                }
            }
        }
        __syncthreads();
    }

#pragma unroll
    for (int nt = 0; nt < 8; nt++) {
        const int col = n0 + wn + nt * 8 + cq * 2;
        const float b0 = __ldg(bias + col), b1 = __ldg(bias + col + 1);
#pragma unroll
        for (int mt = 0; mt < 2; mt++) {
            const int row = m0 + wm + mt * 16 + r;
            *reinterpret_cast<float2*>(C + (size_t)row * ldc + col) =
                make_float2(acc[mt][nt][0] + b0, acc[mt][nt][1] + b1);
            *reinterpret_cast<float2*>(C + (size_t)(row + 8) * ldc + col) =
                make_float2(acc[mt][nt][2] + b0, acc[mt][nt][3] + b1);
        }
    }
}

// ---------------------------------------------------------------------------
// Flash attention with tensor cores. Block = 128 q-rows x 1 head x 1 batch.
// 8 warps, each owns 16 q-rows (full 64-wide n). S: 3xTF32, PV: P single + V split.
// ---------------------------------------------------------------------------
__global__ __launch_bounds__(256) void attn_mma(
    const float* __restrict__ QKV, float* __restrict__ ATT)
{
    extern __shared__ float sm[];
    float* Qs = sm;                 // [128][68] scaled Q
    float* Ks = Qs + 128 * 68;      // [64][68]  K tile  [j][d]
    float* Vs = Ks + 64 * 68;       // [64][68]  V tile transposed [d][j]
    float* Ps = Vs + 64 * 68;       // [128][68] P tile  [m][j]

    const int tid = threadIdx.x, lane = tid & 31, w = tid >> 5;
    const int b = blockIdx.z, h = blockIdx.y, qt = blockIdx.x;
    const int r = lane >> 2, cq = lane & 3;
    const int wrow = w * 16;
    const int qrow0 = b * 2048 + qt * 128;

    // stage Q (pre-scaled by 1/8; exact power of 2)
    {
        const int row = tid >> 1, cb = (tid & 1) * 32;
        const float* qp = QKV + (size_t)(qrow0 + row) * 3072 + h * 64 + cb;
#pragma unroll
        for (int i = 0; i < 8; i++) {
            float4 v = *reinterpret_cast<const float4*>(qp + i * 4);
            v.x *= 0.125f; v.y *= 0.125f; v.z *= 0.125f; v.w *= 0.125f;
            *reinterpret_cast<float4*>(&Qs[row * 68 + cb + i * 4]) = v;
        }
    }

    float o[8][4];
#pragma unroll
    for (int nt = 0; nt < 8; nt++)
#pragma unroll
        for (int i = 0; i < 4; i++) o[nt][i] = 0.f;
    float mr0 = -CUDART_INF_F, mr1 = -CUDART_INF_F;
    float lr0 = 0.f, lr1 = 0.f;

    const int kj = tid >> 2, kcb = (tid & 3) * 16;    // K stage map
    const int vj = tid & 63, vdb = (tid >> 6) * 16;   // V stage map

    for (int kt = 0; kt < 32; kt++) {
        __syncthreads();   // protect Ks/Vs (prev tile readers) and Qs (first iter)
        {
            const float* kp = QKV + (size_t)(b * 2048 + kt * 64 + kj) * 3072
                            + 1024 + h * 64 + kcb;
#pragma unroll
            for (int i = 0; i < 4; i++)
                *reinterpret_cast<float4*>(&Ks[kj * 68 + kcb + i * 4]) =
                    *reinterpret_cast<const float4*>(kp + i * 4);
            const float* vp = QKV + (size_t)(b * 2048 + kt * 64 + vj) * 3072
                            + 2048 + h * 64 + vdb;
#pragma unroll
            for (int i = 0; i < 4; i++) {
                float4 v = *reinterpret_cast<const float4*>(vp + i * 4);
                const int d = vdb + i * 4;
                Vs[(d + 0) * 68 + vj] = v.x; Vs[(d + 1) * 68 + vj] = v.y;
                Vs[(d + 2) * 68 + vj] = v.z; Vs[(d + 3) * 68 + vj] = v.w;
            }
        }
        __syncthreads();

        // ---- S = Qs @ Ks^T (3xTF32) ----
        float s[8][4];
#pragma unroll
        for (int nt = 0; nt < 8; nt++)
#pragma unroll
            for (int i = 0; i < 4; i++) s[nt][i] = 0.f;

#pragma unroll
        for (int ks = 0; ks < 8; ks++) {
            const int kk = ks * 8;
            unsigned ah[4], al[4];
            split_tf(Qs[(wrow + r) * 68 + kk + cq],         ah[0], al[0]);
            split_tf(Qs[(wrow + r + 8) * 68 + kk + cq],     ah[1], al[1]);
            split_tf(Qs[(wrow + r) * 68 + kk + cq + 4],     ah[2], al[2]);
            split_tf(Qs[(wrow + r + 8) * 68 + kk + cq + 4], ah[3], al[3]);
#pragma unroll
            for (int nt = 0; nt < 8; nt++) {
                const int nn = nt * 8 + r;
                unsigned bh0, bl0, bh1, bl1;
                split_tf(Ks[nn * 68 + kk + cq],     bh0, bl0);
                split_tf(Ks[nn * 68 + kk + cq + 4], bh1, bl1);
                mma_tf32(s[nt], ah, bh0, bh1);
                mma_tf32(s[nt], ah, bl0, bl1);
                mma_tf32(s[nt], al, bh0, bh1);
            }
        }

        // ---- online softmax (rows r / r+8 of this warp's 16) ----
        float tm0 = -CUDART_INF_F, tm1 = -CUDART_INF_F;
#pragma unroll
        for (int nt = 0; nt < 8; nt++) {
            tm0 = fmaxf(tm0, fmaxf(s[nt][0], s[nt][1]));
            tm1 = fmaxf(tm1, fmaxf(s[nt][2], s[nt][3]));
        }
        tm0 = fmaxf(tm0, __shfl_xor_sync(0xffffffffu, tm0, 1));
        tm0 = fmaxf(tm0, __shfl_xor_sync(0xffffffffu, tm0, 2));
        tm1 = fmaxf(tm1, __shfl_xor_sync(0xffffffffu, tm1, 1));
        tm1 = fmaxf(tm1, __shfl_xor_sync(0xffffffffu, tm1, 2));

        const float mn0 = fmaxf(mr0, tm0), mn1 = fmaxf(mr1, tm1);
        const float c0 = __expf(mr0 - mn0), c1 = __expf(mr1 - mn1);
        float ps0 = 0.f, ps1 = 0.f;
#pragma unroll
        for (int nt = 0; nt < 8; nt++) {
            const float p00 = __expf(s[nt][0] - mn0);
            const float p01 = __expf(s[nt][1] - mn0);
            const float p10 = __expf(s[nt][2] - mn1);
            const float p11 = __expf(s[nt][3] - mn1);
            ps0 += p00 + p01; ps1 += p10 + p11;
            const int col = nt * 8 + cq * 2;
            *reinterpret_cast<float2*>(&Ps[(wrow + r) * 68 + col]) =
                make_float2(p00, p01);
            *reinterpret_cast<float2*>(&Ps[(wrow + r + 8) * 68 + col]) =
                make_float2(p10, p11);
            o[nt][0] *= c0; o[nt][1] *= c0; o[nt][2] *= c1; o[nt][3] *= c1;
        }
        ps0 += __shfl_xor_sync(0xffffffffu, ps0, 1);
        ps0 += __shfl_xor_sync(0xffffffffu, ps0, 2);
        ps1 += __shfl_xor_sync(0xffffffffu, ps1, 1);
        ps1 += __shfl_xor_sync(0xffffffffu, ps1, 2);
        lr0 = lr0 * c0 + ps0; lr1 = lr1 * c1 + ps1;
        mr0 = mn0; mr1 = mn1;
        __syncwarp();   // Ps is warp-private (rows wrow..wrow+15): warp fence only

        // ---- O += P @ V (P single tf32, V split: 2 mma) ----
#pragma unroll
        for (int ks = 0; ks < 8; ks++) {
            const int kk = ks * 8;
            unsigned a[4];
            a[0] = f2tf(Ps[(wrow + r) * 68 + kk + cq]);
            a[1] = f2tf(Ps[(wrow + r + 8) * 68 + kk + cq]);
            a[2] = f2tf(Ps[(wrow + r) * 68 + kk + cq + 4]);
            a[3] = f2tf(Ps[(wrow + r + 8) * 68 + kk + cq + 4]);
#pragma unroll
            for (int nt = 0; nt < 8; nt++) {
                const int nn = nt * 8 + r;
                unsigned vh0, vl0, vh1, vl1;
                split_tf(Vs[nn * 68 + kk + cq],     vh0, vl0);
                split_tf(Vs[nn * 68 + kk + cq + 4], vh1, vl1);
                mma_tf32(o[nt], a, vh0, vh1);
                mma_tf32(o[nt], a, vl0, vl1);
            }
        }
    }

    const float i0 = 1.f / lr0, i1 = 1.f / lr1;
#pragma unroll
    for (int nt = 0; nt < 8; nt++) {
        const int col = h * 64 + nt * 8 + cq * 2;
        const int row = qrow0 + wrow + r;
        *reinterpret_cast<float2*>(ATT + (size_t)row * 1024 + col) =
            make_float2(o[nt][0] * i0, o[nt][1] * i0);
        *reinterpret_cast<float2*>(ATT + (size_t)(row + 8) * 1024 + col) =
            make_float2(o[nt][2] * i1, o[nt][3] * i1);
    }
}

// ---------------------------------------------------------------------------
extern "C" void kernel_launch(void* const* d_in, const int* in_sizes, int n_in,
                              void* d_out, int out_size)
{
    const float* q   = (const float*)d_in[0];
    const float* Wq  = (const float*)d_in[1];
    const float* bq  = (const float*)d_in[2];
    const float* Wkv = (const float*)d_in[3];
    const float* bkv = (const float*)d_in[4];
    const float* Wo  = (const float*)d_in[5];
    const float* bo  = (const float*)d_in[6];
    float* out = (float*)d_out;

    float* qkv = nullptr;
    float* att = nullptr;
    cudaGetSymbolAddress((void**)&qkv, g_QKV);
    cudaGetSymbolAddress((void**)&att, g_ATT);

    static const int ATTN_SMEM = (128 * 68 + 64 * 68 + 64 * 68 + 128 * 68) * 4;
    cudaFuncSetAttribute(attn_mma, cudaFuncAttributeMaxDynamicSharedMemorySize,
                         ATTN_SMEM);

    // Q projection
    gemm_tf32x3<<<dim3(8, 32), 256>>>(q, 1024, Wq, 1024, bq, qkv, 3072, 1024);
    // KV projection
    gemm_tf32x3<<<dim3(16, 32), 256>>>(q, 1024, Wkv, 2048, bkv, qkv + 1024, 3072, 1024);
    // Attention
    attn_mma<<<dim3(16, 16, 2), 256, ATTN_SMEM>>>(qkv, att);
    // Output projection
    gemm_tf32x3<<<dim3(8, 32), 256>>>(att, 1024, Wo, 1024, bo, out, 1024, 1024);
}

// round 5
// speedup vs baseline: 1.8222x; 1.0775x over previous
#include <cuda_runtime.h>
#include <cuda_bf16.h>
#include <math_constants.h>

// ---------------------------------------------------------------------------
// MHA_962072674722 (b=2, s=2048, dim=1024, 16 heads x 64) — TF32 tensor cores.
// R5: all tf32 splits hoisted out of inner loops (pre-split smem / registers).
// ---------------------------------------------------------------------------

__device__ float g_QKV[4096 * 3072];   // Q|K|V scratch
__device__ float g_ATT[4096 * 1024];   // attention output scratch

// ---- TF32 helpers ---------------------------------------------------------
__device__ __forceinline__ unsigned f2tf(float x) {
    unsigned u;
    asm("cvt.rna.tf32.f32 %0, %1;" : "=r"(u) : "f"(x));
    return u;
}
__device__ __forceinline__ void split_tf(float x, unsigned& h, unsigned& l) {
    h = f2tf(x);
    l = f2tf(x - __uint_as_float(h));
}
__device__ __forceinline__ void mma_tf32(float c[4], const unsigned a[4],
                                         unsigned b0, unsigned b1) {
    asm("mma.sync.aligned.m16n8k8.row.col.f32.tf32.tf32.f32 "
        "{%0,%1,%2,%3},{%4,%5,%6,%7},{%8,%9},{%0,%1,%2,%3};"
        : "+f"(c[0]), "+f"(c[1]), "+f"(c[2]), "+f"(c[3])
        : "r"(a[0]), "r"(a[1]), "r"(a[2]), "r"(a[3]), "r"(b0), "r"(b1));
}

// ---------------------------------------------------------------------------
// 3xTF32 GEMM, pre-split smem. C[M,N] = A[M,K] @ B[K,N] + bias.
// 128x128 block tile, k-tile 32, 8 warps (warp tile 32m x 64n).
// smem: Ah/Al[128][36], Bh/Bl[128][36] (u32 tf32 values) = 73.7 KB dynamic.
// ---------------------------------------------------------------------------
__global__ __launch_bounds__(256) void gemm_tf32x3(
    const float* __restrict__ A, int lda,
    const float* __restrict__ B, int ldb,
    const float* __restrict__ bias,
    float* __restrict__ C, int ldc, int K)
{
    extern __shared__ unsigned gsm[];
    unsigned* Ah = gsm;                 // [128][36]
    unsigned* Al = Ah + 128 * 36;
    unsigned* Bh = Al + 128 * 36;       // [n][k] transposed
    unsigned* Bl = Bh + 128 * 36;

    const int tid = threadIdx.x, lane = tid & 31, w = tid >> 5;
    const int m0 = blockIdx.y * 128, n0 = blockIdx.x * 128;
    const int wm = (w & 3) * 32, wn = (w >> 2) * 64;
    const int r = lane >> 2, cq = lane & 3;

    float acc[2][8][4];
#pragma unroll
    for (int mt = 0; mt < 2; mt++)
#pragma unroll
        for (int nt = 0; nt < 8; nt++)
#pragma unroll
            for (int i = 0; i < 4; i++) acc[mt][nt][i] = 0.f;

    const int arow = tid >> 1, acb = (tid & 1) * 16;
    const int bkk = tid & 31, bnb = (tid >> 5) * 4;

    for (int k0 = 0; k0 < K; k0 += 32) {
        // stage A [128 x 32] -> split hi/lo
#pragma unroll
        for (int i = 0; i < 4; i++) {
            float4 v = *reinterpret_cast<const float4*>(
                A + (size_t)(m0 + arow) * lda + k0 + acb + i * 4);
            unsigned h0, l0, h1, l1, h2, l2, h3, l3;
            split_tf(v.x, h0, l0); split_tf(v.y, h1, l1);
            split_tf(v.z, h2, l2); split_tf(v.w, h3, l3);
            const int off = arow * 36 + acb + i * 4;
            *reinterpret_cast<uint4*>(&Ah[off]) = make_uint4(h0, h1, h2, h3);
            *reinterpret_cast<uint4*>(&Al[off]) = make_uint4(l0, l1, l2, l3);
        }
        // stage B [32 x 128] transposed -> Bh/Bl[n][k]
#pragma unroll
        for (int i = 0; i < 4; i++) {
            const int nn = bnb + i * 32;
            float4 v = *reinterpret_cast<const float4*>(
                B + (size_t)(k0 + bkk) * ldb + n0 + nn);
            unsigned h, l;
            split_tf(v.x, h, l); Bh[(nn + 0) * 36 + bkk] = h; Bl[(nn + 0) * 36 + bkk] = l;
            split_tf(v.y, h, l); Bh[(nn + 1) * 36 + bkk] = h; Bl[(nn + 1) * 36 + bkk] = l;
            split_tf(v.z, h, l); Bh[(nn + 2) * 36 + bkk] = h; Bl[(nn + 2) * 36 + bkk] = l;
            split_tf(v.w, h, l); Bh[(nn + 3) * 36 + bkk] = h; Bl[(nn + 3) * 36 + bkk] = l;
        }
        __syncthreads();

#pragma unroll
        for (int ks = 0; ks < 4; ks++) {
            const int kk = ks * 8;
            unsigned ah[2][4], al[2][4];
#pragma unroll
            for (int mt = 0; mt < 2; mt++) {
                const int mr = wm + mt * 16;
                ah[mt][0] = Ah[(mr + r) * 36 + kk + cq];
                ah[mt][1] = Ah[(mr + r + 8) * 36 + kk + cq];
                ah[mt][2] = Ah[(mr + r) * 36 + kk + cq + 4];
                ah[mt][3] = Ah[(mr + r + 8) * 36 + kk + cq + 4];
                al[mt][0] = Al[(mr + r) * 36 + kk + cq];
                al[mt][1] = Al[(mr + r + 8) * 36 + kk + cq];
                al[mt][2] = Al[(mr + r) * 36 + kk + cq + 4];
                al[mt][3] = Al[(mr + r + 8) * 36 + kk + cq + 4];
            }
#pragma unroll
            for (int nt = 0; nt < 8; nt++) {
                const int nn = (wn + nt * 8 + r) * 36;
                const unsigned bh0 = Bh[nn + kk + cq], bh1 = Bh[nn + kk + cq + 4];
                const unsigned bl0 = Bl[nn + kk + cq], bl1 = Bl[nn + kk + cq + 4];
#pragma unroll
                for (int mt = 0; mt < 2; mt++) {
                    mma_tf32(acc[mt][nt], ah[mt], bh0, bh1);
                    mma_tf32(acc[mt][nt], ah[mt], bl0, bl1);
                    mma_tf32(acc[mt][nt], al[mt], bh0, bh1);
                }
            }
        }
        __syncthreads();
    }

#pragma unroll
    for (int nt = 0; nt < 8; nt++) {
        const int col = n0 + wn + nt * 8 + cq * 2;
        const float b0 = __ldg(bias + col), b1 = __ldg(bias + col + 1);
#pragma unroll
        for (int mt = 0; mt < 2; mt++) {
            const int row = m0 + wm + mt * 16 + r;
            *reinterpret_cast<float2*>(C + (size_t)row * ldc + col) =
                make_float2(acc[mt][nt][0] + b0, acc[mt][nt][1] + b1);
            *reinterpret_cast<float2*>(C + (size_t)(row + 8) * ldc + col) =
                make_float2(acc[mt][nt][2] + b0, acc[mt][nt][3] + b1);
        }
    }
}

// ---------------------------------------------------------------------------
// Flash attention, tensor cores. Block = 128 q-rows x head x batch, 8 warps.
// Q pre-split into REGISTERS (once). K pre-split smem. V single tf32 smem.
// P stored tf32-converted. Zero CVT in the kt mainloop's MMA paths.
// smem: Kh/Kl[64][68], Vt[64][68], Ps[128][68] = 87 KB dynamic.
// ---------------------------------------------------------------------------
__global__ __launch_bounds__(256) void attn_mma(
    const float* __restrict__ QKV, float* __restrict__ ATT)
{
    extern __shared__ unsigned asm_[];
    unsigned* Kh = asm_;                // [64][68]
    unsigned* Kl = Kh + 64 * 68;
    unsigned* Vt = Kl + 64 * 68;        // [d][j] single tf32
    unsigned* Ps = Vt + 64 * 68;        // [128][68] tf32 P (float stage at init)
    float*    PsF = reinterpret_cast<float*>(Ps);

    const int tid = threadIdx.x, lane = tid & 31, w = tid >> 5;
    const int b = blockIdx.z, h = blockIdx.y, qt = blockIdx.x;
    const int r = lane >> 2, cq = lane & 3;
    const int wrow = w * 16;
    const int qrow0 = b * 2048 + qt * 128;

    // --- stage scaled Q into PsF (coalesced), then split to registers ---
    {
        const int row = tid >> 1, cb = (tid & 1) * 32;
        const float* qp = QKV + (size_t)(qrow0 + row) * 3072 + h * 64 + cb;
#pragma unroll
        for (int i = 0; i < 8; i++) {
            float4 v = *reinterpret_cast<const float4*>(qp + i * 4);
            v.x *= 0.125f; v.y *= 0.125f; v.z *= 0.125f; v.w *= 0.125f;
            *reinterpret_cast<float4*>(&PsF[row * 68 + cb + i * 4]) = v;
        }
    }
    __syncthreads();

    unsigned qh[8][4], ql[8][4];
#pragma unroll
    for (int ks = 0; ks < 8; ks++) {
        const int kk = ks * 8;
        split_tf(PsF[(wrow + r) * 68 + kk + cq],         qh[ks][0], ql[ks][0]);
        split_tf(PsF[(wrow + r + 8) * 68 + kk + cq],     qh[ks][1], ql[ks][1]);
        split_tf(PsF[(wrow + r) * 68 + kk + cq + 4],     qh[ks][2], ql[ks][2]);
        split_tf(PsF[(wrow + r + 8) * 68 + kk + cq + 4], qh[ks][3], ql[ks][3]);
    }

    float o[8][4];
#pragma unroll
    for (int nt = 0; nt < 8; nt++)
#pragma unroll
        for (int i = 0; i < 4; i++) o[nt][i] = 0.f;
    float mr0 = -CUDART_INF_F, mr1 = -CUDART_INF_F;
    float lr0 = 0.f, lr1 = 0.f;

    const int kj = tid >> 2, kcb = (tid & 3) * 16;    // K stage map
    const int vj = tid & 63, vdb = (tid >> 6) * 16;   // V stage map

    for (int kt = 0; kt < 32; kt++) {
        __syncthreads();   // all readers of prev K/V tile (and Q-frag reads) done
        {
            const float* kp = QKV + (size_t)(b * 2048 + kt * 64 + kj) * 3072
                            + 1024 + h * 64 + kcb;
#pragma unroll
            for (int i = 0; i < 4; i++) {
                float4 v = *reinterpret_cast<const float4*>(kp + i * 4);
                unsigned hh, ll;
                const int off = kj * 68 + kcb + i * 4;
                split_tf(v.x, hh, ll); Kh[off + 0] = hh; Kl[off + 0] = ll;
                split_tf(v.y, hh, ll); Kh[off + 1] = hh; Kl[off + 1] = ll;
                split_tf(v.z, hh, ll); Kh[off + 2] = hh; Kl[off + 2] = ll;
                split_tf(v.w, hh, ll); Kh[off + 3] = hh; Kl[off + 3] = ll;
            }
            const float* vp = QKV + (size_t)(b * 2048 + kt * 64 + vj) * 3072
                            + 2048 + h * 64 + vdb;
#pragma unroll
            for (int i = 0; i < 4; i++) {
                float4 v = *reinterpret_cast<const float4*>(vp + i * 4);
                const int d = vdb + i * 4;
                Vt[(d + 0) * 68 + vj] = f2tf(v.x);
                Vt[(d + 1) * 68 + vj] = f2tf(v.y);
                Vt[(d + 2) * 68 + vj] = f2tf(v.z);
                Vt[(d + 3) * 68 + vj] = f2tf(v.w);
            }
        }
        __syncthreads();

        // ---- S = Q @ K^T (3xTF32; Q frags already in regs) ----
        float s[8][4];
#pragma unroll
        for (int nt = 0; nt < 8; nt++)
#pragma unroll
            for (int i = 0; i < 4; i++) s[nt][i] = 0.f;

#pragma unroll
        for (int ks = 0; ks < 8; ks++) {
            const int kk = ks * 8;
#pragma unroll
            for (int nt = 0; nt < 8; nt++) {
                const int nn = (nt * 8 + r) * 68;
                const unsigned bh0 = Kh[nn + kk + cq], bh1 = Kh[nn + kk + cq + 4];
                const unsigned bl0 = Kl[nn + kk + cq], bl1 = Kl[nn + kk + cq + 4];
                mma_tf32(s[nt], qh[ks], bh0, bh1);
                mma_tf32(s[nt], qh[ks], bl0, bl1);
                mma_tf32(s[nt], ql[ks], bh0, bh1);
            }
        }

        // ---- online softmax ----
        float tm0 = -CUDART_INF_F, tm1 = -CUDART_INF_F;
#pragma unroll
        for (int nt = 0; nt < 8; nt++) {
            tm0 = fmaxf(tm0, fmaxf(s[nt][0], s[nt][1]));
            tm1 = fmaxf(tm1, fmaxf(s[nt][2], s[nt][3]));
        }
        tm0 = fmaxf(tm0, __shfl_xor_sync(0xffffffffu, tm0, 1));
        tm0 = fmaxf(tm0, __shfl_xor_sync(0xffffffffu, tm0, 2));
        tm1 = fmaxf(tm1, __shfl_xor_sync(0xffffffffu, tm1, 1));
        tm1 = fmaxf(tm1, __shfl_xor_sync(0xffffffffu, tm1, 2));

        const float mn0 = fmaxf(mr0, tm0), mn1 = fmaxf(mr1, tm1);
        const float c0 = __expf(mr0 - mn0), c1 = __expf(mr1 - mn1);
        float ps0 = 0.f, ps1 = 0.f;
#pragma unroll
        for (int nt = 0; nt < 8; nt++) {
            const float p00 = __expf(s[nt][0] - mn0);
            const float p01 = __expf(s[nt][1] - mn0);
            const float p10 = __expf(s[nt][2] - mn1);
            const float p11 = __expf(s[nt][3] - mn1);
            ps0 += p00 + p01; ps1 += p10 + p11;
            const int col = nt * 8 + cq * 2;
            *reinterpret_cast<uint2*>(&Ps[(wrow + r) * 68 + col]) =
                make_uint2(f2tf(p00), f2tf(p01));
            *reinterpret_cast<uint2*>(&Ps[(wrow + r + 8) * 68 + col]) =
                make_uint2(f2tf(p10), f2tf(p11));
            o[nt][0] *= c0; o[nt][1] *= c0; o[nt][2] *= c1; o[nt][3] *= c1;
        }
        ps0 += __shfl_xor_sync(0xffffffffu, ps0, 1);
        ps0 += __shfl_xor_sync(0xffffffffu, ps0, 2);
        ps1 += __shfl_xor_sync(0xffffffffu, ps1, 1);
        ps1 += __shfl_xor_sync(0xffffffffu, ps1, 2);
        lr0 = lr0 * c0 + ps0; lr1 = lr1 * c1 + ps1;
        mr0 = mn0; mr1 = mn1;
        __syncwarp();   // Ps rows wrow..wrow+15 are warp-private

        // ---- O += P @ V (single tf32 each: 1 MMA) ----
#pragma unroll
        for (int ks = 0; ks < 8; ks++) {
            const int kk = ks * 8;
            unsigned a[4];
            a[0] = Ps[(wrow + r) * 68 + kk + cq];
            a[1] = Ps[(wrow + r + 8) * 68 + kk + cq];
            a[2] = Ps[(wrow + r) * 68 + kk + cq + 4];
            a[3] = Ps[(wrow + r + 8) * 68 + kk + cq + 4];
#pragma unroll
            for (int nt = 0; nt < 8; nt++) {
                const int nn = (nt * 8 + r) * 68;
                mma_tf32(o[nt], a, Vt[nn + kk + cq], Vt[nn + kk + cq + 4]);
            }
        }
    }

    const float i0 = 1.f / lr0, i1 = 1.f / lr1;
#pragma unroll
    for (int nt = 0; nt < 8; nt++) {
        const int col = h * 64 + nt * 8 + cq * 2;
        const int row = qrow0 + wrow + r;
        *reinterpret_cast<float2*>(ATT + (size_t)row * 1024 + col) =
            make_float2(o[nt][0] * i0, o[nt][1] * i0);
        *reinterpret_cast<float2*>(ATT + (size_t)(row + 8) * 1024 + col) =
            make_float2(o[nt][2] * i1, o[nt][3] * i1);
    }
}

// ---------------------------------------------------------------------------
extern "C" void kernel_launch(void* const* d_in, const int* in_sizes, int n_in,
                              void* d_out, int out_size)
{
    const float* q   = (const float*)d_in[0];
    const float* Wq  = (const float*)d_in[1];
    const float* bq  = (const float*)d_in[2];
    const float* Wkv = (const float*)d_in[3];
    const float* bkv = (const float*)d_in[4];
    const float* Wo  = (const float*)d_in[5];
    const float* bo  = (const float*)d_in[6];
    float* out = (float*)d_out;

    float* qkv = nullptr;
    float* att = nullptr;
    cudaGetSymbolAddress((void**)&qkv, g_QKV);
    cudaGetSymbolAddress((void**)&att, g_ATT);

    const int GEMM_SMEM = 4 * 128 * 36 * 4;                       // 73728
    const int ATTN_SMEM = (3 * 64 * 68 + 128 * 68) * 4;           // 87040
    cudaFuncSetAttribute(gemm_tf32x3, cudaFuncAttributeMaxDynamicSharedMemorySize,
                         GEMM_SMEM);
    cudaFuncSetAttribute(attn_mma, cudaFuncAttributeMaxDynamicSharedMemorySize,
                         ATTN_SMEM);

    // Q projection
    gemm_tf32x3<<<dim3(8, 32), 256, GEMM_SMEM>>>(q, 1024, Wq, 1024, bq,
                                                 qkv, 3072, 1024);
    // KV projection
    gemm_tf32x3<<<dim3(16, 32), 256, GEMM_SMEM>>>(q, 1024, Wkv, 2048, bkv,
                                                  qkv + 1024, 3072, 1024);
    // Attention
    attn_mma<<<dim3(16, 16, 2), 256, ATTN_SMEM>>>(qkv, att);
    // Output projection
    gemm_tf32x3<<<dim3(8, 32), 256, GEMM_SMEM>>>(att, 1024, Wo, 1024, bo,
                                                 out, 1024, 1024);
}

// round 6
// speedup vs baseline: 2.7884x; 1.5302x over previous
#include <cuda_runtime.h>
#include <cuda_bf16.h>
#include <math_constants.h>

// ---------------------------------------------------------------------------
// MHA_962072674722 (b=2, s=2048, dim=1024, 16 heads x 64)
// R6: 3-term BF16 split on m16n8k16 HMMA for all GEMM-like work (2x tf32 rate),
//     PV stays single-TF32. GEMM forced to 2 CTA/SM.
// ---------------------------------------------------------------------------

__device__ float g_QKV[4096 * 3072];   // Q|K|V scratch
__device__ float g_ATT[4096 * 1024];   // attention output scratch

// ---- helpers --------------------------------------------------------------
__device__ __forceinline__ unsigned f2tf(float x) {
    unsigned u;
    asm("cvt.rna.tf32.f32 %0, %1;" : "=r"(u) : "f"(x));
    return u;
}
__device__ __forceinline__ unsigned pack_bf(float lo, float hi) {
    __nv_bfloat162 t = __floats2bfloat162_rn(lo, hi);
    return *reinterpret_cast<unsigned*>(&t);
}
__device__ __forceinline__ void split_bf(float x, __nv_bfloat16& h, __nv_bfloat16& l) {
    h = __float2bfloat16(x);
    l = __float2bfloat16(x - __bfloat162float(h));
}
__device__ __forceinline__ void mma_bf16(float c[4], const unsigned a[4],
                                         unsigned b0, unsigned b1) {
    asm("mma.sync.aligned.m16n8k16.row.col.f32.bf16.bf16.f32 "
        "{%0,%1,%2,%3},{%4,%5,%6,%7},{%8,%9},{%0,%1,%2,%3};"
        : "+f"(c[0]), "+f"(c[1]), "+f"(c[2]), "+f"(c[3])
        : "r"(a[0]), "r"(a[1]), "r"(a[2]), "r"(a[3]), "r"(b0), "r"(b1));
}
__device__ __forceinline__ void mma_tf32(float c[4], const unsigned a[4],
                                         unsigned b0, unsigned b1) {
    asm("mma.sync.aligned.m16n8k8.row.col.f32.tf32.tf32.f32 "
        "{%0,%1,%2,%3},{%4,%5,%6,%7},{%8,%9},{%0,%1,%2,%3};"
        : "+f"(c[0]), "+f"(c[1]), "+f"(c[2]), "+f"(c[3])
        : "r"(a[0]), "r"(a[1]), "r"(a[2]), "r"(a[3]), "r"(b0), "r"(b1));
}

// ---------------------------------------------------------------------------
// 3xBF16 GEMM: C[M,N] = A[M,K] @ B[K,N] + bias.
// 128x128 block tile, k-tile 32, 8 warps (warp tile 32m x 64n).
// smem: Ah/Al[128][40], Bh/Bl[128][40] bf16 = 40 KB. 2 CTAs/SM.
// ---------------------------------------------------------------------------
__global__ __launch_bounds__(256, 2) void gemm_bf16x3(
    const float* __restrict__ A, int lda,
    const float* __restrict__ B, int ldb,
    const float* __restrict__ bias,
    float* __restrict__ C, int ldc, int K)
{
    extern __shared__ __nv_bfloat16 gsm[];
    __nv_bfloat16* Ah = gsm;                  // [128][40]
    __nv_bfloat16* Al = Ah + 128 * 40;
    __nv_bfloat16* Bh = Al + 128 * 40;        // [n][k] transposed
    __nv_bfloat16* Bl = Bh + 128 * 40;

    const int tid = threadIdx.x, lane = tid & 31, w = tid >> 5;
    const int m0 = blockIdx.y * 128, n0 = blockIdx.x * 128;
    const int wm = (w & 3) * 32, wn = (w >> 2) * 64;
    const int r = lane >> 2, cq = lane & 3;

    float acc[2][8][4];
#pragma unroll
    for (int mt = 0; mt < 2; mt++)
#pragma unroll
        for (int nt = 0; nt < 8; nt++)
#pragma unroll
            for (int i = 0; i < 4; i++) acc[mt][nt][i] = 0.f;

    const int arow = tid >> 1, acb = (tid & 1) * 16;
    const int bkk = tid & 31, bnb = (tid >> 5) * 4;

    for (int k0 = 0; k0 < K; k0 += 32) {
        // stage A [128 x 32] -> split hi/lo bf16
#pragma unroll
        for (int i = 0; i < 4; i++) {
            float4 v = *reinterpret_cast<const float4*>(
                A + (size_t)(m0 + arow) * lda + k0 + acb + i * 4);
            __nv_bfloat16 h0, l0, h1, l1, h2, l2, h3, l3;
            split_bf(v.x, h0, l0); split_bf(v.y, h1, l1);
            split_bf(v.z, h2, l2); split_bf(v.w, h3, l3);
            const int off = arow * 40 + acb + i * 4;
            __nv_bfloat162 ph0 = {h0, h1}, ph1 = {h2, h3};
            __nv_bfloat162 pl0 = {l0, l1}, pl1 = {l2, l3};
            *reinterpret_cast<uint2*>(&Ah[off]) =
                make_uint2(*(unsigned*)&ph0, *(unsigned*)&ph1);
            *reinterpret_cast<uint2*>(&Al[off]) =
                make_uint2(*(unsigned*)&pl0, *(unsigned*)&pl1);
        }
        // stage B [32 x 128] transposed -> Bh/Bl[n][k]
#pragma unroll
        for (int i = 0; i < 4; i++) {
            const int nn = bnb + i * 32;
            float4 v = *reinterpret_cast<const float4*>(
                B + (size_t)(k0 + bkk) * ldb + n0 + nn);
            __nv_bfloat16 h, l;
            split_bf(v.x, h, l); Bh[(nn + 0) * 40 + bkk] = h; Bl[(nn + 0) * 40 + bkk] = l;
            split_bf(v.y, h, l); Bh[(nn + 1) * 40 + bkk] = h; Bl[(nn + 1) * 40 + bkk] = l;
            split_bf(v.z, h, l); Bh[(nn + 2) * 40 + bkk] = h; Bl[(nn + 2) * 40 + bkk] = l;
            split_bf(v.w, h, l); Bh[(nn + 3) * 40 + bkk] = h; Bl[(nn + 3) * 40 + bkk] = l;
        }
        __syncthreads();

#pragma unroll
        for (int ks = 0; ks < 2; ks++) {
            const int kk = ks * 16;
            unsigned ah[2][4], al[2][4];
#pragma unroll
            for (int mt = 0; mt < 2; mt++) {
                const int mr = wm + mt * 16;
                ah[mt][0] = *(unsigned*)&Ah[(mr + r) * 40 + kk + cq * 2];
                ah[mt][1] = *(unsigned*)&Ah[(mr + r + 8) * 40 + kk + cq * 2];
                ah[mt][2] = *(unsigned*)&Ah[(mr + r) * 40 + kk + cq * 2 + 8];
                ah[mt][3] = *(unsigned*)&Ah[(mr + r + 8) * 40 + kk + cq * 2 + 8];
                al[mt][0] = *(unsigned*)&Al[(mr + r) * 40 + kk + cq * 2];
                al[mt][1] = *(unsigned*)&Al[(mr + r + 8) * 40 + kk + cq * 2];
                al[mt][2] = *(unsigned*)&Al[(mr + r) * 40 + kk + cq * 2 + 8];
                al[mt][3] = *(unsigned*)&Al[(mr + r + 8) * 40 + kk + cq * 2 + 8];
            }
#pragma unroll
            for (int nt = 0; nt < 8; nt++) {
                const int base = (wn + nt * 8 + r) * 40 + kk;
                const unsigned bh0 = *(unsigned*)&Bh[base + cq * 2];
                const unsigned bh1 = *(unsigned*)&Bh[base + cq * 2 + 8];
                const unsigned bl0 = *(unsigned*)&Bl[base + cq * 2];
                const unsigned bl1 = *(unsigned*)&Bl[base + cq * 2 + 8];
#pragma unroll
                for (int mt = 0; mt < 2; mt++) {
                    mma_bf16(acc[mt][nt], ah[mt], bh0, bh1);
                    mma_bf16(acc[mt][nt], ah[mt], bl0, bl1);
                    mma_bf16(acc[mt][nt], al[mt], bh0, bh1);
                }
            }
        }
        __syncthreads();
    }

#pragma unroll
    for (int nt = 0; nt < 8; nt++) {
        const int col = n0 + wn + nt * 8 + cq * 2;
        const float b0 = __ldg(bias + col), b1 = __ldg(bias + col + 1);
#pragma unroll
        for (int mt = 0; mt < 2; mt++) {
            const int row = m0 + wm + mt * 16 + r;
            *reinterpret_cast<float2*>(C + (size_t)row * ldc + col) =
                make_float2(acc[mt][nt][0] + b0, acc[mt][nt][1] + b1);
            *reinterpret_cast<float2*>(C + (size_t)(row + 8) * ldc + col) =
                make_float2(acc[mt][nt][2] + b0, acc[mt][nt][3] + b1);
        }
    }
}

// ---------------------------------------------------------------------------
// Flash attention. Block = 128 q-rows x head x batch, 8 warps.
// S = Q@K^T via 3xBF16 (Q pre-split in regs, K pre-split bf16 smem).
// PV via single-TF32 (P tf32 smem, V tf32 smem).
// smem: Kh/Kl[64][72] bf16, Vt[64][68] u32, Ps[128][68] u32 = 70.7 KB.
// ---------------------------------------------------------------------------
__global__ __launch_bounds__(256) void attn_mma(
    const float* __restrict__ QKV, float* __restrict__ ATT)
{
    extern __shared__ char smraw[];
    __nv_bfloat16* Kh = reinterpret_cast<__nv_bfloat16*>(smraw);   // [64][72]
    __nv_bfloat16* Kl = Kh + 64 * 72;
    unsigned* Vt = reinterpret_cast<unsigned*>(Kl + 64 * 72);      // [d][j] tf32
    unsigned* Ps = Vt + 64 * 68;                                   // [128][68]
    float*    PsF = reinterpret_cast<float*>(Ps);

    const int tid = threadIdx.x, lane = tid & 31, w = tid >> 5;
    const int b = blockIdx.z, h = blockIdx.y, qt = blockIdx.x;
    const int r = lane >> 2, cq = lane & 3;
    const int wrow = w * 16;
    const int qrow0 = b * 2048 + qt * 128;

    // --- stage scaled Q into PsF (coalesced), then split to bf16 registers ---
    {
        const int row = tid >> 1, cb = (tid & 1) * 32;
        const float* qp = QKV + (size_t)(qrow0 + row) * 3072 + h * 64 + cb;
#pragma unroll
        for (int i = 0; i < 8; i++) {
            float4 v = *reinterpret_cast<const float4*>(qp + i * 4);
            v.x *= 0.125f; v.y *= 0.125f; v.z *= 0.125f; v.w *= 0.125f;
            *reinterpret_cast<float4*>(&PsF[row * 68 + cb + i * 4]) = v;
        }
    }
    __syncthreads();

    unsigned qh[4][4], ql[4][4];
#pragma unroll
    for (int ks = 0; ks < 4; ks++) {
        const int kk = ks * 16;
#pragma unroll
        for (int fi = 0; fi < 4; fi++) {
            const int rr = wrow + r + (fi & 1) * 8;
            const int cc = kk + cq * 2 + (fi >> 1) * 8;
            float x0 = PsF[rr * 68 + cc], x1 = PsF[rr * 68 + cc + 1];
            __nv_bfloat16 h0, l0, h1, l1;
            split_bf(x0, h0, l0); split_bf(x1, h1, l1);
            __nv_bfloat162 ph = {h0, h1}, pl = {l0, l1};
            qh[ks][fi] = *(unsigned*)&ph;
            ql[ks][fi] = *(unsigned*)&pl;
        }
    }

    float o[8][4];
#pragma unroll
    for (int nt = 0; nt < 8; nt++)
#pragma unroll
        for (int i = 0; i < 4; i++) o[nt][i] = 0.f;
    float mr0 = -CUDART_INF_F, mr1 = -CUDART_INF_F;
    float lr0 = 0.f, lr1 = 0.f;

    const int kj = tid >> 2, kcb = (tid & 3) * 16;    // K stage map
    const int vj = tid & 63, vdb = (tid >> 6) * 16;   // V stage map

    for (int kt = 0; kt < 32; kt++) {
        __syncthreads();   // prev tile readers done (and Q staging on iter 0)
        {
            const float* kp = QKV + (size_t)(b * 2048 + kt * 64 + kj) * 3072
                            + 1024 + h * 64 + kcb;
#pragma unroll
            for (int i = 0; i < 4; i++) {
                float4 v = *reinterpret_cast<const float4*>(kp + i * 4);
                __nv_bfloat16 h0, l0, h1, l1, h2, l2, h3, l3;
                split_bf(v.x, h0, l0); split_bf(v.y, h1, l1);
                split_bf(v.z, h2, l2); split_bf(v.w, h3, l3);
                const int off = kj * 72 + kcb + i * 4;
                __nv_bfloat162 ph0 = {h0, h1}, ph1 = {h2, h3};
                __nv_bfloat162 pl0 = {l0, l1}, pl1 = {l2, l3};
                *reinterpret_cast<uint2*>(&Kh[off]) =
                    make_uint2(*(unsigned*)&ph0, *(unsigned*)&ph1);
                *reinterpret_cast<uint2*>(&Kl[off]) =
                    make_uint2(*(unsigned*)&pl0, *(unsigned*)&pl1);
            }
            const float* vp = QKV + (size_t)(b * 2048 + kt * 64 + vj) * 3072
                            + 2048 + h * 64 + vdb;
#pragma unroll
            for (int i = 0; i < 4; i++) {
                float4 v = *reinterpret_cast<const float4*>(vp + i * 4);
                const int d = vdb + i * 4;
                Vt[(d + 0) * 68 + vj] = f2tf(v.x);
                Vt[(d + 1) * 68 + vj] = f2tf(v.y);
                Vt[(d + 2) * 68 + vj] = f2tf(v.z);
                Vt[(d + 3) * 68 + vj] = f2tf(v.w);
            }
        }
        __syncthreads();

        // ---- S = Q @ K^T (3xBF16, k16) ----
        float s[8][4];
#pragma unroll
        for (int nt = 0; nt < 8; nt++)
#pragma unroll
            for (int i = 0; i < 4; i++) s[nt][i] = 0.f;

#pragma unroll
        for (int ks = 0; ks < 4; ks++) {
            const int kk = ks * 16;
#pragma unroll
            for (int nt = 0; nt < 8; nt++) {
                const int base = (nt * 8 + r) * 72 + kk;
                const unsigned bh0 = *(unsigned*)&Kh[base + cq * 2];
                const unsigned bh1 = *(unsigned*)&Kh[base + cq * 2 + 8];
                const unsigned bl0 = *(unsigned*)&Kl[base + cq * 2];
                const unsigned bl1 = *(unsigned*)&Kl[base + cq * 2 + 8];
                mma_bf16(s[nt], qh[ks], bh0, bh1);
                mma_bf16(s[nt], qh[ks], bl0, bl1);
                mma_bf16(s[nt], ql[ks], bh0, bh1);
            }
        }

        // ---- online softmax ----
        float tm0 = -CUDART_INF_F, tm1 = -CUDART_INF_F;
#pragma unroll
        for (int nt = 0; nt < 8; nt++) {
            tm0 = fmaxf(tm0, fmaxf(s[nt][0], s[nt][1]));
            tm1 = fmaxf(tm1, fmaxf(s[nt][2], s[nt][3]));
        }
        tm0 = fmaxf(tm0, __shfl_xor_sync(0xffffffffu, tm0, 1));
        tm0 = fmaxf(tm0, __shfl_xor_sync(0xffffffffu, tm0, 2));
        tm1 = fmaxf(tm1, __shfl_xor_sync(0xffffffffu, tm1, 1));
        tm1 = fmaxf(tm1, __shfl_xor_sync(0xffffffffu, tm1, 2));

        const float mn0 = fmaxf(mr0, tm0), mn1 = fmaxf(mr1, tm1);
        const float c0 = __expf(mr0 - mn0), c1 = __expf(mr1 - mn1);
        float ps0 = 0.f, ps1 = 0.f;
#pragma unroll
        for (int nt = 0; nt < 8; nt++) {
            const float p00 = __expf(s[nt][0] - mn0);
            const float p01 = __expf(s[nt][1] - mn0);
            const float p10 = __expf(s[nt][2] - mn1);
            const float p11 = __expf(s[nt][3] - mn1);
            ps0 += p00 + p01; ps1 += p10 + p11;
            const int col = nt * 8 + cq * 2;
            *reinterpret_cast<uint2*>(&Ps[(wrow + r) * 68 + col]) =
                make_uint2(f2tf(p00), f2tf(p01));
            *reinterpret_cast<uint2*>(&Ps[(wrow + r + 8) * 68 + col]) =
                make_uint2(f2tf(p10), f2tf(p11));
            o[nt][0] *= c0; o[nt][1] *= c0; o[nt][2] *= c1; o[nt][3] *= c1;
        }
        ps0 += __shfl_xor_sync(0xffffffffu, ps0, 1);
        ps0 += __shfl_xor_sync(0xffffffffu, ps0, 2);
        ps1 += __shfl_xor_sync(0xffffffffu, ps1, 1);
        ps1 += __shfl_xor_sync(0xffffffffu, ps1, 2);
        lr0 = lr0 * c0 + ps0; lr1 = lr1 * c1 + ps1;
        mr0 = mn0; mr1 = mn1;
        __syncwarp();   // Ps rows wrow..wrow+15 are warp-private

        // ---- O += P @ V (single tf32 each: 1 MMA per k8) ----
#pragma unroll
        for (int ks = 0; ks < 8; ks++) {
            const int kk = ks * 8;
            unsigned a[4];
            a[0] = Ps[(wrow + r) * 68 + kk + cq];
            a[1] = Ps[(wrow + r + 8) * 68 + kk + cq];
            a[2] = Ps[(wrow + r) * 68 + kk + cq + 4];
            a[3] = Ps[(wrow + r + 8) * 68 + kk + cq + 4];
#pragma unroll
            for (int nt = 0; nt < 8; nt++) {
                const int nn = (nt * 8 + r) * 68;
                mma_tf32(o[nt], a, Vt[nn + kk + cq], Vt[nn + kk + cq + 4]);
            }
        }
    }

    const float i0 = 1.f / lr0, i1 = 1.f / lr1;
#pragma unroll
    for (int nt = 0; nt < 8; nt++) {
        const int col = h * 64 + nt * 8 + cq * 2;
        const int row = qrow0 + wrow + r;
        *reinterpret_cast<float2*>(ATT + (size_t)row * 1024 + col) =
            make_float2(o[nt][0] * i0, o[nt][1] * i0);
        *reinterpret_cast<float2*>(ATT + (size_t)(row + 8) * 1024 + col) =
            make_float2(o[nt][2] * i1, o[nt][3] * i1);
    }
}

// ---------------------------------------------------------------------------
extern "C" void kernel_launch(void* const* d_in, const int* in_sizes, int n_in,
                              void* d_out, int out_size)
{
    const float* q   = (const float*)d_in[0];
    const float* Wq  = (const float*)d_in[1];
    const float* bq  = (const float*)d_in[2];
    const float* Wkv = (const float*)d_in[3];
    const float* bkv = (const float*)d_in[4];
    const float* Wo  = (const float*)d_in[5];
    const float* bo  = (const float*)d_in[6];
    float* out = (float*)d_out;

    float* qkv = nullptr;
    float* att = nullptr;
    cudaGetSymbolAddress((void**)&qkv, g_QKV);
    cudaGetSymbolAddress((void**)&att, g_ATT);

    const int GEMM_SMEM = 4 * 128 * 40 * 2;                           // 40960
    const int ATTN_SMEM = (2 * 64 * 72) * 2 + (64 * 68 + 128 * 68) * 4; // 70656
    cudaFuncSetAttribute(gemm_bf16x3, cudaFuncAttributeMaxDynamicSharedMemorySize,
                         GEMM_SMEM);
    cudaFuncSetAttribute(attn_mma, cudaFuncAttributeMaxDynamicSharedMemorySize,
                         ATTN_SMEM);

    // Q projection
    gemm_bf16x3<<<dim3(8, 32), 256, GEMM_SMEM>>>(q, 1024, Wq, 1024, bq,
                                                 qkv, 3072, 1024);
    // KV projection
    gemm_bf16x3<<<dim3(16, 32), 256, GEMM_SMEM>>>(q, 1024, Wkv, 2048, bkv,
                                                  qkv + 1024, 3072, 1024);
    // Attention
    attn_mma<<<dim3(16, 16, 2), 256, ATTN_SMEM>>>(qkv, att);
    // Output projection
    gemm_bf16x3<<<dim3(8, 32), 256, GEMM_SMEM>>>(att, 1024, Wo, 1024, bo,
                                                 out, 1024, 1024);
}

// round 10
// speedup vs baseline: 3.3503x; 1.2015x over previous
#include <cuda_runtime.h>
#include <cuda_bf16.h>
#include <math_constants.h>

// ---------------------------------------------------------------------------
// MHA_962072674722 (b=2, s=2048, dim=1024, 16 heads x 64)
// R8 (= R7 resubmit after infra failure): pre-split bf16 operands everywhere
// (split exactly once), cp.async double-buffered GEMM, format-targeted
// epilogues, CVT-free mainloops.
// ---------------------------------------------------------------------------

// ---- pre-split operand buffers (split exactly once per value) -------------
__device__ __nv_bfloat16 g_qh[4096 * 1024],  g_ql[4096 * 1024];    // input q split
__device__ __nv_bfloat16 g_WqhT[1024 * 1024], g_WqlT[1024 * 1024]; // W^T splits
__device__ __nv_bfloat16 g_WkhT[1024 * 1024], g_WklT[1024 * 1024];
__device__ __nv_bfloat16 g_WvhT[1024 * 1024], g_WvlT[1024 * 1024];
__device__ __nv_bfloat16 g_WohT[1024 * 1024], g_WolT[1024 * 1024];
__device__ __nv_bfloat16 g_Qh[4096 * 1024],  g_Ql[4096 * 1024];    // scaled Q split
__device__ __nv_bfloat16 g_Kh[4096 * 1024],  g_Kl[4096 * 1024];    // K split
__device__ float         g_VT[4096 * 1024];                        // V tf32, [b,h,d,j]
__device__ __nv_bfloat16 g_ATTh[4096 * 1024], g_ATTl[4096 * 1024]; // attn out split

// ---- helpers --------------------------------------------------------------
__device__ __forceinline__ unsigned f2tf(float x) {
    unsigned u;
    asm("cvt.rna.tf32.f32 %0, %1;" : "=r"(u) : "f"(x));
    return u;
}
__device__ __forceinline__ void split_bf(float x, __nv_bfloat16& h, __nv_bfloat16& l) {
    h = __float2bfloat16(x);
    l = __float2bfloat16(x - __bfloat162float(h));
}
__device__ __forceinline__ unsigned pack2(__nv_bfloat16 a, __nv_bfloat16 b) {
    __nv_bfloat162 p = {a, b};
    return *reinterpret_cast<unsigned*>(&p);
}
__device__ __forceinline__ void mma_bf16(float c[4], const unsigned a[4],
                                         unsigned b0, unsigned b1) {
    asm("mma.sync.aligned.m16n8k16.row.col.f32.bf16.bf16.f32 "
        "{%0,%1,%2,%3},{%4,%5,%6,%7},{%8,%9},{%0,%1,%2,%3};"
        : "+f"(c[0]), "+f"(c[1]), "+f"(c[2]), "+f"(c[3])
        : "r"(a[0]), "r"(a[1]), "r"(a[2]), "r"(a[3]), "r"(b0), "r"(b1));
}
__device__ __forceinline__ void mma_tf32(float c[4], const unsigned a[4],
                                         unsigned b0, unsigned b1) {
    asm("mma.sync.aligned.m16n8k8.row.col.f32.tf32.tf32.f32 "
        "{%0,%1,%2,%3},{%4,%5,%6,%7},{%8,%9},{%0,%1,%2,%3};"
        : "+f"(c[0]), "+f"(c[1]), "+f"(c[2]), "+f"(c[3])
        : "r"(a[0]), "r"(a[1]), "r"(a[2]), "r"(a[3]), "r"(b0), "r"(b1));
}
__device__ __forceinline__ void cp16(void* dst, const void* src) {
    unsigned d = (unsigned)__cvta_generic_to_shared(dst);
    asm volatile("cp.async.cg.shared.global [%0], [%1], 16;"
                 :: "r"(d), "l"(src) : "memory");
}

// ---------------------------------------------------------------------------
// Prep: elementwise fp32 -> (hi, lo) bf16 split. n4 = elems/4.
// ---------------------------------------------------------------------------
__global__ __launch_bounds__(256) void split_mat(
    const float* __restrict__ in, __nv_bfloat16* __restrict__ h,
    __nv_bfloat16* __restrict__ l, int n4)
{
    int i = blockIdx.x * blockDim.x + threadIdx.x;
    if (i >= n4) return;
    float4 v = reinterpret_cast<const float4*>(in)[i];
    __nv_bfloat16 h0, l0, h1, l1, h2, l2, h3, l3;
    split_bf(v.x, h0, l0); split_bf(v.y, h1, l1);
    split_bf(v.z, h2, l2); split_bf(v.w, h3, l3);
    reinterpret_cast<uint2*>(h)[i] = make_uint2(pack2(h0, h1), pack2(h2, h3));
    reinterpret_cast<uint2*>(l)[i] = make_uint2(pack2(l0, l1), pack2(l2, l3));
}

// ---------------------------------------------------------------------------
// Prep: split + transpose weight block. W [1024 k][ldw], cols [col0, col0+1024)
// -> hT/lT [1024 n][1024 k] bf16.
// ---------------------------------------------------------------------------
__global__ __launch_bounds__(256) void split_transpose(
    const float* __restrict__ W, int ldw, int col0,
    __nv_bfloat16* __restrict__ hT, __nv_bfloat16* __restrict__ lT)
{
    __shared__ float t[32][33];
    const int tx = threadIdx.x, ty = threadIdx.y;
    const int co = blockIdx.x * 32, k0 = blockIdx.y * 32;
#pragma unroll
    for (int i = ty; i < 32; i += 8)
        t[i][tx] = W[(size_t)(k0 + i) * ldw + col0 + co + tx];
    __syncthreads();
#pragma unroll
    for (int i = ty; i < 32; i += 8) {
        float v = t[tx][i];                 // = W[k0+tx][col0+co+i]
        __nv_bfloat16 h, l;
        split_bf(v, h, l);
        hT[(size_t)(co + i) * 1024 + k0 + tx] = h;
        lT[(size_t)(co + i) * 1024 + k0 + tx] = l;
    }
}

// ---------------------------------------------------------------------------
// Pipelined 3xBF16 GEMM on pre-split operands.
// C[4096,1024] = A[4096,1024] @ B^T ; A,B given as (hi,lo) bf16, B row = n.
// 128x128 tile, k-tile 32, 8 warps, cp.async 2-stage. 2 CTA/SM.
// MODE 0: fp32 out (+bias). MODE 1: split bf16 out ((acc+bias)*scale).
// MODE 2: tf32 fp32 out, transposed to [b,h,d,j] (for attention V).
// ---------------------------------------------------------------------------
#define ARR   (128 * 40)
#define STAGE (4 * ARR)

template <int MODE>
__global__ __launch_bounds__(256, 2) void gemm_ps(
    const __nv_bfloat16* __restrict__ Ah, const __nv_bfloat16* __restrict__ Al,
    const __nv_bfloat16* __restrict__ BhT, const __nv_bfloat16* __restrict__ BlT,
    const float* __restrict__ bias, float scale,
    float* __restrict__ outF,
    __nv_bfloat16* __restrict__ outH, __nv_bfloat16* __restrict__ outL)
{
    extern __shared__ __nv_bfloat16 sm[];
    const int tid = threadIdx.x, lane = tid & 31, w = tid >> 5;
    const int m0 = blockIdx.y * 128, n0 = blockIdx.x * 128;
    const int wm = (w & 3) * 32, wn = (w >> 2) * 64;
    const int r = lane >> 2, cq = lane & 3;

    float acc[2][8][4];
#pragma unroll
    for (int mt = 0; mt < 2; mt++)
#pragma unroll
        for (int nt = 0; nt < 8; nt++)
#pragma unroll
            for (int i = 0; i < 4; i++) acc[mt][nt][i] = 0.f;

    const int srow = tid >> 1, scb = (tid & 1) * 16;
    const __nv_bfloat16* gAh = Ah + (size_t)(m0 + srow) * 1024 + scb;
    const __nv_bfloat16* gAl = Al + (size_t)(m0 + srow) * 1024 + scb;
    const __nv_bfloat16* gBh = BhT + (size_t)(n0 + srow) * 1024 + scb;
    const __nv_bfloat16* gBl = BlT + (size_t)(n0 + srow) * 1024 + scb;
    const int so = srow * 40 + scb;

    auto stage = [&](int kt, int buf) {
        __nv_bfloat16* s = sm + buf * STAGE;
        const int go = kt * 32;
        cp16(s + so,               gAh + go); cp16(s + so + 8,               gAh + go + 8);
        cp16(s + ARR + so,         gAl + go); cp16(s + ARR + so + 8,         gAl + go + 8);
        cp16(s + 2 * ARR + so,     gBh + go); cp16(s + 2 * ARR + so + 8,     gBh + go + 8);
        cp16(s + 3 * ARR + so,     gBl + go); cp16(s + 3 * ARR + so + 8,     gBl + go + 8);
        asm volatile("cp.async.commit_group;" ::: "memory");
    };

    stage(0, 0);
    stage(1, 1);

    for (int kt = 0; kt < 32; kt++) {
        if (kt + 1 < 32) asm volatile("cp.async.wait_group 1;" ::: "memory");
        else             asm volatile("cp.async.wait_group 0;" ::: "memory");
        __syncthreads();

        const __nv_bfloat16* s = sm + (kt & 1) * STAGE;
#pragma unroll
        for (int ks = 0; ks < 2; ks++) {
            const int kk = ks * 16;
            unsigned ah[2][4], al4[2][4];
#pragma unroll
            for (int mt = 0; mt < 2; mt++) {
                const int mr = wm + mt * 16;
                ah[mt][0]  = *(const unsigned*)&s[(mr + r) * 40 + kk + cq * 2];
                ah[mt][1]  = *(const unsigned*)&s[(mr + r + 8) * 40 + kk + cq * 2];
                ah[mt][2]  = *(const unsigned*)&s[(mr + r) * 40 + kk + cq * 2 + 8];
                ah[mt][3]  = *(const unsigned*)&s[(mr + r + 8) * 40 + kk + cq * 2 + 8];
                al4[mt][0] = *(const unsigned*)&s[ARR + (mr + r) * 40 + kk + cq * 2];
                al4[mt][1] = *(const unsigned*)&s[ARR + (mr + r + 8) * 40 + kk + cq * 2];
                al4[mt][2] = *(const unsigned*)&s[ARR + (mr + r) * 40 + kk + cq * 2 + 8];
                al4[mt][3] = *(const unsigned*)&s[ARR + (mr + r + 8) * 40 + kk + cq * 2 + 8];
            }
#pragma unroll
            for (int nt = 0; nt < 8; nt++) {
                const int base = (wn + nt * 8 + r) * 40 + kk + cq * 2;
                const unsigned bh0 = *(const unsigned*)&s[2 * ARR + base];
                const unsigned bh1 = *(const unsigned*)&s[2 * ARR + base + 8];
                const unsigned bl0 = *(const unsigned*)&s[3 * ARR + base];
                const unsigned bl1 = *(const unsigned*)&s[3 * ARR + base + 8];
#pragma unroll
                for (int mt = 0; mt < 2; mt++) {
                    mma_bf16(acc[mt][nt], ah[mt],  bh0, bh1);
                    mma_bf16(acc[mt][nt], ah[mt],  bl0, bl1);
                    mma_bf16(acc[mt][nt], al4[mt], bh0, bh1);
                }
            }
        }
        __syncthreads();
        if (kt + 2 < 32) stage(kt + 2, kt & 1);
    }

    // ---- epilogue -------------------------------------------------------
#pragma unroll
    for (int nt = 0; nt < 8; nt++) {
        const int col = n0 + wn + nt * 8 + cq * 2;
        const float b0 = __ldg(bias + col), b1 = __ldg(bias + col + 1);
#pragma unroll
        for (int mt = 0; mt < 2; mt++) {
            const int row = m0 + wm + mt * 16 + r;
            float v00 = acc[mt][nt][0] + b0, v01 = acc[mt][nt][1] + b1;
            float v10 = acc[mt][nt][2] + b0, v11 = acc[mt][nt][3] + b1;
            if (MODE == 0) {
                *reinterpret_cast<float2*>(outF + (size_t)row * 1024 + col) =
                    make_float2(v00, v01);
                *reinterpret_cast<float2*>(outF + (size_t)(row + 8) * 1024 + col) =
                    make_float2(v10, v11);
            } else if (MODE == 1) {
                v00 *= scale; v01 *= scale; v10 *= scale; v11 *= scale;
                __nv_bfloat16 h0, l0, h1, l1;
                split_bf(v00, h0, l0); split_bf(v01, h1, l1);
                *(unsigned*)&outH[(size_t)row * 1024 + col] = pack2(h0, h1);
                *(unsigned*)&outL[(size_t)row * 1024 + col] = pack2(l0, l1);
                split_bf(v10, h0, l0); split_bf(v11, h1, l1);
                *(unsigned*)&outH[(size_t)(row + 8) * 1024 + col] = pack2(h0, h1);
                *(unsigned*)&outL[(size_t)(row + 8) * 1024 + col] = pack2(l0, l1);
            } else {
                // V: transposed tf32 store  VT[((b*16+h)*64+d)*2048 + j]
                const size_t base = (size_t)((row >> 11) * 16 + (col >> 6)) * 64;
                const int d = col & 63;
                outF[(base + d) * 2048 + (row & 2047)]     = __uint_as_float(f2tf(v00));
                outF[(base + d + 1) * 2048 + (row & 2047)] = __uint_as_float(f2tf(v01));
                outF[(base + d) * 2048 + ((row + 8) & 2047)]     = __uint_as_float(f2tf(v10));
                outF[(base + d + 1) * 2048 + ((row + 8) & 2047)] = __uint_as_float(f2tf(v11));
            }
        }
    }
}

// ---------------------------------------------------------------------------
// Flash attention on pre-split operands. Block = 128 q-rows x head x batch.
// Q frags: direct LDG (pre-scaled split). K: raw copies of pre-split bf16.
// V: raw copies of pre-rounded tf32 in [d][j] layout. Epilogue: split store.
// smem: Khs/Kls[64][72] bf16, Vs[64][68] u32, Ps[128][68] u32 = 70.7 KB.
// ---------------------------------------------------------------------------
__global__ __launch_bounds__(256) void attn_mma(
    const __nv_bfloat16* __restrict__ Qh, const __nv_bfloat16* __restrict__ Ql,
    const __nv_bfloat16* __restrict__ Kh, const __nv_bfloat16* __restrict__ Kl,
    const float* __restrict__ VT,
    __nv_bfloat16* __restrict__ ATTh, __nv_bfloat16* __restrict__ ATTl)
{
    extern __shared__ char smraw[];
    __nv_bfloat16* Khs = reinterpret_cast<__nv_bfloat16*>(smraw);  // [64][72]
    __nv_bfloat16* Kls = Khs + 64 * 72;
    unsigned* Vs = reinterpret_cast<unsigned*>(Kls + 64 * 72);     // [64][68] tf32
    unsigned* Ps = Vs + 64 * 68;                                   // [128][68] tf32

    const int tid = threadIdx.x, lane = tid & 31, w = tid >> 5;
    const int b = blockIdx.z, h = blockIdx.y, qt = blockIdx.x;
    const int r = lane >> 2, cq = lane & 3;
    const int wrow = w * 16;
    const int qrow0 = b * 2048 + qt * 128;

    // --- Q fragments: direct from pre-split global (once) ---
    unsigned qh[4][4], ql4[4][4];
#pragma unroll
    for (int ks = 0; ks < 4; ks++)
#pragma unroll
        for (int fi = 0; fi < 4; fi++) {
            const int rr = qrow0 + wrow + r + (fi & 1) * 8;
            const int cc = h * 64 + ks * 16 + cq * 2 + (fi >> 1) * 8;
            qh[ks][fi]  = *(const unsigned*)&Qh[(size_t)rr * 1024 + cc];
            ql4[ks][fi] = *(const unsigned*)&Ql[(size_t)rr * 1024 + cc];
        }

    float o[8][4];
#pragma unroll
    for (int nt = 0; nt < 8; nt++)
#pragma unroll
        for (int i = 0; i < 4; i++) o[nt][i] = 0.f;
    float mr0 = -CUDART_INF_F, mr1 = -CUDART_INF_F;
    float lr0 = 0.f, lr1 = 0.f;

    const int kj = tid >> 2, kcb = (tid & 3) * 16;
    const int vd = tid >> 2, vjb = (tid & 3) * 16;
    const float* vbase = VT + (size_t)((b * 16 + h) * 64 + vd) * 2048 + vjb;

    for (int kt = 0; kt < 32; kt++) {
        __syncthreads();   // prev tile readers done
        {
            const size_t krow = (size_t)(b * 2048 + kt * 64 + kj) * 1024 + h * 64 + kcb;
            *(uint4*)&Khs[kj * 72 + kcb]     = *(const uint4*)&Kh[krow];
            *(uint4*)&Khs[kj * 72 + kcb + 8] = *(const uint4*)&Kh[krow + 8];
            *(uint4*)&Kls[kj * 72 + kcb]     = *(const uint4*)&Kl[krow];
            *(uint4*)&Kls[kj * 72 + kcb + 8] = *(const uint4*)&Kl[krow + 8];
            const float* vp = vbase + kt * 64;
#pragma unroll
            for (int i = 0; i < 4; i++)
                *(float4*)&Vs[vd * 68 + vjb + i * 4] = *(const float4*)(vp + i * 4);
        }
        __syncthreads();

        // ---- S = Q @ K^T (3xBF16, k16) ----
        float s[8][4];
#pragma unroll
        for (int nt = 0; nt < 8; nt++)
#pragma unroll
            for (int i = 0; i < 4; i++) s[nt][i] = 0.f;

#pragma unroll
        for (int ks = 0; ks < 4; ks++) {
            const int kk = ks * 16;
#pragma unroll
            for (int nt = 0; nt < 8; nt++) {
                const int base = (nt * 8 + r) * 72 + kk + cq * 2;
                const unsigned bh0 = *(const unsigned*)&Khs[base];
                const unsigned bh1 = *(const unsigned*)&Khs[base + 8];
                const unsigned bl0 = *(const unsigned*)&Kls[base];
                const unsigned bl1 = *(const unsigned*)&Kls[base + 8];
                mma_bf16(s[nt], qh[ks],  bh0, bh1);
                mma_bf16(s[nt], qh[ks],  bl0, bl1);
                mma_bf16(s[nt], ql4[ks], bh0, bh1);
            }
        }

        // ---- online softmax ----
        float tm0 = -CUDART_INF_F, tm1 = -CUDART_INF_F;
#pragma unroll
        for (int nt = 0; nt < 8; nt++) {
            tm0 = fmaxf(tm0, fmaxf(s[nt][0], s[nt][1]));
            tm1 = fmaxf(tm1, fmaxf(s[nt][2], s[nt][3]));
        }
        tm0 = fmaxf(tm0, __shfl_xor_sync(0xffffffffu, tm0, 1));
        tm0 = fmaxf(tm0, __shfl_xor_sync(0xffffffffu, tm0, 2));
        tm1 = fmaxf(tm1, __shfl_xor_sync(0xffffffffu, tm1, 1));
        tm1 = fmaxf(tm1, __shfl_xor_sync(0xffffffffu, tm1, 2));

        const float mn0 = fmaxf(mr0, tm0), mn1 = fmaxf(mr1, tm1);
        const float c0 = __expf(mr0 - mn0), c1 = __expf(mr1 - mn1);
        float ps0 = 0.f, ps1 = 0.f;
#pragma unroll
        for (int nt = 0; nt < 8; nt++) {
            const float p00 = __expf(s[nt][0] - mn0);
            const float p01 = __expf(s[nt][1] - mn0);
            const float p10 = __expf(s[nt][2] - mn1);
            const float p11 = __expf(s[nt][3] - mn1);
            ps0 += p00 + p01; ps1 += p10 + p11;
            const int col = nt * 8 + cq * 2;
            *reinterpret_cast<uint2*>(&Ps[(wrow + r) * 68 + col]) =
                make_uint2(f2tf(p00), f2tf(p01));
            *reinterpret_cast<uint2*>(&Ps[(wrow + r + 8) * 68 + col]) =
                make_uint2(f2tf(p10), f2tf(p11));
            o[nt][0] *= c0; o[nt][1] *= c0; o[nt][2] *= c1; o[nt][3] *= c1;
        }
        ps0 += __shfl_xor_sync(0xffffffffu, ps0, 1);
        ps0 += __shfl_xor_sync(0xffffffffu, ps0, 2);
        ps1 += __shfl_xor_sync(0xffffffffu, ps1, 1);
        ps1 += __shfl_xor_sync(0xffffffffu, ps1, 2);
        lr0 = lr0 * c0 + ps0; lr1 = lr1 * c1 + ps1;
        mr0 = mn0; mr1 = mn1;
        __syncwarp();   // Ps rows wrow..wrow+15 are warp-private

        // ---- O += P @ V (single tf32, V bits pre-rounded) ----
#pragma unroll
        for (int ks = 0; ks < 8; ks++) {
            const int kk = ks * 8;
            unsigned a[4];
            a[0] = Ps[(wrow + r) * 68 + kk + cq];
            a[1] = Ps[(wrow + r + 8) * 68 + kk + cq];
            a[2] = Ps[(wrow + r) * 68 + kk + cq + 4];
            a[3] = Ps[(wrow + r + 8) * 68 + kk + cq + 4];
#pragma unroll
            for (int nt = 0; nt < 8; nt++) {
                const int nn = (nt * 8 + r) * 68;
                mma_tf32(o[nt], a, Vs[nn + kk + cq], Vs[nn + kk + cq + 4]);
            }
        }
    }

    // ---- epilogue: split store to ATTh/ATTl ----
    const float i0 = 1.f / lr0, i1 = 1.f / lr1;
#pragma unroll
    for (int nt = 0; nt < 8; nt++) {
        const int col = h * 64 + nt * 8 + cq * 2;
        const int row = qrow0 + wrow + r;
        __nv_bfloat16 h0, l0, h1, l1;
        split_bf(o[nt][0] * i0, h0, l0); split_bf(o[nt][1] * i0, h1, l1);
        *(unsigned*)&ATTh[(size_t)row * 1024 + col] = pack2(h0, h1);
        *(unsigned*)&ATTl[(size_t)row * 1024 + col] = pack2(l0, l1);
        split_bf(o[nt][2] * i1, h0, l0); split_bf(o[nt][3] * i1, h1, l1);
        *(unsigned*)&ATTh[(size_t)(row + 8) * 1024 + col] = pack2(h0, h1);
        *(unsigned*)&ATTl[(size_t)(row + 8) * 1024 + col] = pack2(l0, l1);
    }
}

// ---------------------------------------------------------------------------
extern "C" void kernel_launch(void* const* d_in, const int* in_sizes, int n_in,
                              void* d_out, int out_size)
{
    const float* q   = (const float*)d_in[0];
    const float* Wq  = (const float*)d_in[1];
    const float* bq  = (const float*)d_in[2];
    const float* Wkv = (const float*)d_in[3];
    const float* bkv = (const float*)d_in[4];
    const float* Wo  = (const float*)d_in[5];
    const float* bo  = (const float*)d_in[6];
    float* out = (float*)d_out;

    __nv_bfloat16 *qh, *ql, *WqhT, *WqlT, *WkhT, *WklT, *WvhT, *WvlT, *WohT, *WolT;
    __nv_bfloat16 *Qh, *Ql, *Kh, *Kl, *ATTh, *ATTl;
    float *VT;
    cudaGetSymbolAddress((void**)&qh, g_qh);     cudaGetSymbolAddress((void**)&ql, g_ql);
    cudaGetSymbolAddress((void**)&WqhT, g_WqhT); cudaGetSymbolAddress((void**)&WqlT, g_WqlT);
    cudaGetSymbolAddress((void**)&WkhT, g_WkhT); cudaGetSymbolAddress((void**)&WklT, g_WklT);
    cudaGetSymbolAddress((void**)&WvhT, g_WvhT); cudaGetSymbolAddress((void**)&WvlT, g_WvlT);
    cudaGetSymbolAddress((void**)&WohT, g_WohT); cudaGetSymbolAddress((void**)&WolT, g_WolT);
    cudaGetSymbolAddress((void**)&Qh, g_Qh);     cudaGetSymbolAddress((void**)&Ql, g_Ql);
    cudaGetSymbolAddress((void**)&Kh, g_Kh);     cudaGetSymbolAddress((void**)&Kl, g_Kl);
    cudaGetSymbolAddress((void**)&VT, g_VT);
    cudaGetSymbolAddress((void**)&ATTh, g_ATTh); cudaGetSymbolAddress((void**)&ATTl, g_ATTl);

    const int GEMM_SMEM = 2 * STAGE * 2;            // 81920 B
    const int ATTN_SMEM = (2 * 64 * 72) * 2 + (64 * 68 + 128 * 68) * 4;  // 70656 B
    cudaFuncSetAttribute(gemm_ps<0>, cudaFuncAttributeMaxDynamicSharedMemorySize, GEMM_SMEM);
    cudaFuncSetAttribute(gemm_ps<1>, cudaFuncAttributeMaxDynamicSharedMemorySize, GEMM_SMEM);
    cudaFuncSetAttribute(gemm_ps<2>, cudaFuncAttributeMaxDynamicSharedMemorySize, GEMM_SMEM);
    cudaFuncSetAttribute(attn_mma, cudaFuncAttributeMaxDynamicSharedMemorySize, ATTN_SMEM);

    // --- prep: split activations, split+transpose weights ---
    split_mat<<<4096, 256>>>(q, qh, ql, 4096 * 1024 / 4);
    split_transpose<<<dim3(32, 32), dim3(32, 8)>>>(Wq, 1024, 0, WqhT, WqlT);
    split_transpose<<<dim3(32, 32), dim3(32, 8)>>>(Wkv, 2048, 0, WkhT, WklT);
    split_transpose<<<dim3(32, 32), dim3(32, 8)>>>(Wkv, 2048, 1024, WvhT, WvlT);
    split_transpose<<<dim3(32, 32), dim3(32, 8)>>>(Wo, 1024, 0, WohT, WolT);

    // --- projections ---
    gemm_ps<1><<<dim3(8, 32), 256, GEMM_SMEM>>>(qh, ql, WqhT, WqlT, bq, 0.125f,
                                                nullptr, Qh, Ql);
    gemm_ps<1><<<dim3(8, 32), 256, GEMM_SMEM>>>(qh, ql, WkhT, WklT, bkv, 1.0f,
                                                nullptr, Kh, Kl);
    gemm_ps<2><<<dim3(8, 32), 256, GEMM_SMEM>>>(qh, ql, WvhT, WvlT, bkv + 1024, 1.0f,
                                                VT, nullptr, nullptr);
    // --- attention ---
    attn_mma<<<dim3(16, 16, 2), 256, ATTN_SMEM>>>(Qh, Ql, Kh, Kl, VT, ATTh, ATTl);
    // --- output projection ---
    gemm_ps<0><<<dim3(8, 32), 256, GEMM_SMEM>>>(ATTh, ATTl, WohT, WolT, bo, 1.0f,
                                                out, nullptr, nullptr);
}